// round 2
// baseline (speedup 1.0000x reference)
#include <cuda_runtime.h>
#include <cuda_bf16.h>
#include <cstdint>

// SDDMM: out[e] = <src_feat[src_idx[e]], dst_feat[dst_idx[e]]>, D=64.
// 16 lanes per edge, float4 gathers (256B/row fully coalesced per half-warp),
// shfl-xor reduction within the 16-lane group.

static constexpr int D = 64;
static constexpr int LANES_PER_EDGE = 16;
static constexpr int THREADS = 256;

__global__ __launch_bounds__(THREADS)
void sddmm_dot_kernel(const int* __restrict__ src_idx,
                      const int* __restrict__ dst_idx,
                      const float* __restrict__ src_feat,
                      const float* __restrict__ dst_feat,
                      float* __restrict__ out,
                      int n_edges) {
    int gid   = blockIdx.x * THREADS + threadIdx.x;
    int e_raw = gid >> 4;                 // edge index
    int lane  = gid & 15;                 // lane within 16-group
    // Clamp instead of early-exit: keeps all warp lanes active through the
    // shuffles (full-warp masks), tail lanes just redo the last edge.
    int e = e_raw < n_edges ? e_raw : n_edges - 1;

    int si = __ldg(src_idx + e);          // broadcast load across the group
    int di = __ldg(dst_idx + e);

    const float4* s = reinterpret_cast<const float4*>(src_feat + (size_t)si * D) + lane;
    const float4* d = reinterpret_cast<const float4*>(dst_feat + (size_t)di * D) + lane;
    float4 a = __ldg(s);
    float4 b = __ldg(d);

    float p = a.x * b.x + a.y * b.y + a.z * b.z + a.w * b.w;

    // Reduce across the 16-lane group (XOR distances <= 8 stay in-group).
    p += __shfl_xor_sync(0xFFFFFFFFu, p, 8);
    p += __shfl_xor_sync(0xFFFFFFFFu, p, 4);
    p += __shfl_xor_sync(0xFFFFFFFFu, p, 2);
    p += __shfl_xor_sync(0xFFFFFFFFu, p, 1);

    if (lane == 0 && e_raw < n_edges) out[e_raw] = p;
}

extern "C" void kernel_launch(void* const* d_in, const int* in_sizes, int n_in,
                              void* d_out, int out_size) {
    const int*   src_idx  = (const int*)d_in[0];
    const int*   dst_idx  = (const int*)d_in[1];
    const float* src_feat = (const float*)d_in[2];
    const float* dst_feat = (const float*)d_in[3];
    float*       out      = (float*)d_out;

    int n_edges = in_sizes[0];
    long long total_threads = (long long)n_edges * LANES_PER_EDGE;
    int blocks = (int)((total_threads + THREADS - 1) / THREADS);

    sddmm_dot_kernel<<<blocks, THREADS>>>(src_idx, dst_idx, src_feat, dst_feat,
                                          out, n_edges);
}

// round 3
// speedup vs baseline: 1.6735x; 1.6735x over previous
#include <cuda_runtime.h>
#include <cuda_bf16.h>
#include <cstdint>

// SDDMM: out[e] = <src_feat[src_idx[e]], dst_feat[dst_idx[e]]>, D=64.
// 8 lanes per edge-pair group, 2 edges per thread, 8 independent float4
// gathers per thread (MLP=8), 3-step shfl reduction, float2 store.

static constexpr int D = 64;
static constexpr int THREADS = 256;

__global__ __launch_bounds__(THREADS)
void sddmm_dot_kernel(const int* __restrict__ src_idx,
                      const int* __restrict__ dst_idx,
                      const float* __restrict__ src_feat,
                      const float* __restrict__ dst_feat,
                      float* __restrict__ out,
                      int n_edges) {
    int gid  = blockIdx.x * THREADS + threadIdx.x;
    int pair = gid >> 3;            // edge-pair index
    int lane = gid & 7;             // lane within 8-group

    int n_pairs = (n_edges + 1) >> 1;
    int p_clamped = pair < n_pairs ? pair : n_pairs - 1;

    int e0 = 2 * p_clamped;
    int e1 = e0 + 1;
    int e1c = e1 < n_edges ? e1 : e0;   // clamp odd tail

    int s0i = __ldg(src_idx + e0);
    int d0i = __ldg(dst_idx + e0);
    int s1i = __ldg(src_idx + e1c);
    int d1i = __ldg(dst_idx + e1c);

    const float4* s0 = reinterpret_cast<const float4*>(src_feat + (size_t)s0i * D);
    const float4* d0 = reinterpret_cast<const float4*>(dst_feat + (size_t)d0i * D);
    const float4* s1 = reinterpret_cast<const float4*>(src_feat + (size_t)s1i * D);
    const float4* d1 = reinterpret_cast<const float4*>(dst_feat + (size_t)d1i * D);

    // 8 independent 16B loads — maximize MLP before any math.
    float4 a0 = __ldg(s0 + lane);
    float4 a1 = __ldg(s0 + lane + 8);
    float4 b0 = __ldg(d0 + lane);
    float4 b1 = __ldg(d0 + lane + 8);
    float4 c0 = __ldg(s1 + lane);
    float4 c1 = __ldg(s1 + lane + 8);
    float4 f0 = __ldg(d1 + lane);
    float4 f1 = __ldg(d1 + lane + 8);

    float p0 = a0.x * b0.x + a0.y * b0.y + a0.z * b0.z + a0.w * b0.w
             + a1.x * b1.x + a1.y * b1.y + a1.z * b1.z + a1.w * b1.w;
    float p1 = c0.x * f0.x + c0.y * f0.y + c0.z * f0.z + c0.w * f0.w
             + c1.x * f1.x + c1.y * f1.y + c1.z * f1.z + c1.w * f1.w;

    // Reduce across the 8-lane group; the two chains are independent and
    // overlap in the pipeline.
    p0 += __shfl_xor_sync(0xFFFFFFFFu, p0, 4);
    p1 += __shfl_xor_sync(0xFFFFFFFFu, p1, 4);
    p0 += __shfl_xor_sync(0xFFFFFFFFu, p0, 2);
    p1 += __shfl_xor_sync(0xFFFFFFFFu, p1, 2);
    p0 += __shfl_xor_sync(0xFFFFFFFFu, p0, 1);
    p1 += __shfl_xor_sync(0xFFFFFFFFu, p1, 1);

    if (lane == 0 && pair < n_pairs) {
        if (e1 < n_edges) {
            // e0 is even -> 8B-aligned float2 store covering both edges.
            *reinterpret_cast<float2*>(out + e0) = make_float2(p0, p1);
        } else {
            out[e0] = p0;
        }
    }
}

extern "C" void kernel_launch(void* const* d_in, const int* in_sizes, int n_in,
                              void* d_out, int out_size) {
    const int*   src_idx  = (const int*)d_in[0];
    const int*   dst_idx  = (const int*)d_in[1];
    const float* src_feat = (const float*)d_in[2];
    const float* dst_feat = (const float*)d_in[3];
    float*       out      = (float*)d_out;

    int n_edges = in_sizes[0];
    int n_pairs = (n_edges + 1) / 2;
    long long total_threads = (long long)n_pairs * 8;
    int blocks = (int)((total_threads + THREADS - 1) / THREADS);

    sddmm_dot_kernel<<<blocks, THREADS>>>(src_idx, dst_idx, src_feat, dst_feat,
                                          out, n_edges);
}

// round 4
// speedup vs baseline: 1.6829x; 1.0056x over previous
#include <cuda_runtime.h>
#include <cuda_bf16.h>
#include <cstdint>

// SDDMM: out[e] = <src_feat[src_idx[e]], dst_feat[dst_idx[e]]>, D=64.
// 8 lanes per edge-pair group, 2 edges per thread, 8 independent float4
// gathers per thread (MLP=8). Parity-merged butterfly: 3 shfls reduce BOTH
// edges; lane 0 holds dot(e0), lane 4 holds dot(e1).

static constexpr int D = 64;
static constexpr int THREADS = 256;

__global__ __launch_bounds__(THREADS)
void sddmm_dot_kernel(const int* __restrict__ src_idx,
                      const int* __restrict__ dst_idx,
                      const float* __restrict__ src_feat,
                      const float* __restrict__ dst_feat,
                      float* __restrict__ out,
                      int n_edges) {
    int gid  = blockIdx.x * THREADS + threadIdx.x;
    int pair = gid >> 3;            // edge-pair index
    int lane = gid & 7;             // lane within 8-group

    int n_pairs = (n_edges + 1) >> 1;
    bool live = pair < n_pairs;
    int p_clamped = live ? pair : n_pairs - 1;

    int e0 = 2 * p_clamped;
    int e1 = e0 + 1;
    int e1c = e1 < n_edges ? e1 : e0;   // clamp odd tail

    int s0i = __ldg(src_idx + e0);
    int d0i = __ldg(dst_idx + e0);
    int s1i = __ldg(src_idx + e1c);
    int d1i = __ldg(dst_idx + e1c);

    const float4* s0 = reinterpret_cast<const float4*>(src_feat + (size_t)s0i * D);
    const float4* d0 = reinterpret_cast<const float4*>(dst_feat + (size_t)d0i * D);
    const float4* s1 = reinterpret_cast<const float4*>(src_feat + (size_t)s1i * D);
    const float4* d1 = reinterpret_cast<const float4*>(dst_feat + (size_t)d1i * D);

    // 8 independent 16B loads — maximize MLP before any math.
    float4 a0 = __ldg(s0 + lane);
    float4 a1 = __ldg(s0 + lane + 8);
    float4 b0 = __ldg(d0 + lane);
    float4 b1 = __ldg(d0 + lane + 8);
    float4 c0 = __ldg(s1 + lane);
    float4 c1 = __ldg(s1 + lane + 8);
    float4 f0 = __ldg(d1 + lane);
    float4 f1 = __ldg(d1 + lane + 8);

    float p0 = a0.x * b0.x + a0.y * b0.y + a0.z * b0.z + a0.w * b0.w
             + a1.x * b1.x + a1.y * b1.y + a1.z * b1.z + a1.w * b1.w;
    float p1 = c0.x * f0.x + c0.y * f0.y + c0.z * f0.z + c0.w * f0.w
             + c1.x * f1.x + c1.y * f1.y + c1.z * f1.z + c1.w * f1.w;

    // Parity-merged reduction: 3 shfls reduce both 8-lane sums.
    // Step 1: send the edge you will NOT keep across the xor-4 boundary.
    bool hi = (lane & 4) != 0;
    float send = hi ? p0 : p1;
    float keep = hi ? p1 : p0;
    float z = keep + __shfl_xor_sync(0xFFFFFFFFu, send, 4);
    // lanes 0-3 now hold p0 partials, lanes 4-7 hold p1 partials.
    z += __shfl_xor_sync(0xFFFFFFFFu, z, 2);
    z += __shfl_xor_sync(0xFFFFFFFFu, z, 1);
    // lane 0 -> dot(e0), lane 4 -> dot(e1)

    if (live) {
        if (lane == 0) out[e0] = z;
        else if (lane == 4 && e1 < n_edges) out[e1] = z;
    }
}

extern "C" void kernel_launch(void* const* d_in, const int* in_sizes, int n_in,
                              void* d_out, int out_size) {
    const int*   src_idx  = (const int*)d_in[0];
    const int*   dst_idx  = (const int*)d_in[1];
    const float* src_feat = (const float*)d_in[2];
    const float* dst_feat = (const float*)d_in[3];
    float*       out      = (float*)d_out;

    int n_edges = in_sizes[0];
    int n_pairs = (n_edges + 1) / 2;
    long long total_threads = (long long)n_pairs * 8;
    int blocks = (int)((total_threads + THREADS - 1) / THREADS);

    sddmm_dot_kernel<<<blocks, THREADS>>>(src_idx, dst_idx, src_feat, dst_feat,
                                          out, n_edges);
}